// round 8
// baseline (speedup 1.0000x reference)
#include <cuda_runtime.h>
#include <cstdint>

// Grid is 128^3 logical; density is padded to 130^3 (1-voxel zero border).
#define GRID_N (128*128*128)          // 2,097,152
#define PADW   130
#define PGRID_N (PADW*PADW*PADW)      // 2,197,000
#define SCAN_BLOCKS 1024              // 1024 * 256 * 8 = 2,097,152

__device__ float g_pdensity[PGRID_N];
__device__ __align__(8) unsigned char g_active[GRID_N];
__device__ unsigned int g_blocksums[SCAN_BLOCKS];
__device__ unsigned int g_count;
__device__ unsigned int g_cells[GRID_N];

// neighbor offsets in padded grid: di*16900 + dj*130 + dk, t=(di+1)*9+(dj+1)*3+(dk+1)
// (three trailing zeros so depth-3 prefetch can read t+3 unconditionally)
__constant__ int c_off[30] = {
    -17031,-17030,-17029,-16901,-16900,-16899,-16771,-16770,-16769,
      -131,  -130,  -129,    -1,     0,     1,   129,   130,   131,
     16769, 16770, 16771, 16899, 16900, 16901, 17029, 17030, 17031,
     0, 0, 0};

// ---------------------------------------------------------------------------
// Scatter features into padded density grid + mark active (3x3x3) flags.
__global__ void scatter_kernel(const int* __restrict__ idx,
                               const float* __restrict__ feat, int n) {
    int i = blockIdx.x * blockDim.x + threadIdx.x;
    if (i >= n) return;
    int x = idx[3*i], y = idx[3*i+1], z = idx[3*i+2];
    int plin = ((x + 1) * PADW + (y + 1)) * PADW + (z + 1);
    atomicAdd(&g_pdensity[plin], feat[i]);
    #pragma unroll
    for (int di = -1; di <= 1; di++)
        #pragma unroll
        for (int dj = -1; dj <= 1; dj++)
            #pragma unroll
            for (int dk = -1; dk <= 1; dk++) {
                int nx = x + di, ny = y + dj, nz = z + dk;
                if ((unsigned)nx < 128u && (unsigned)ny < 128u && (unsigned)nz < 128u)
                    g_active[(nx << 14) | (ny << 7) | nz] = 1;  // racy stores of 1: fine
            }
}

// ---- prefix scan over 2M flags: 2 kernels -------------------------------
__global__ void scan1_kernel() {
    int base = blockIdx.x * 2048 + threadIdx.x * 8;
    unsigned long long v = *(const unsigned long long*)(g_active + base);
    unsigned s = (unsigned)((v * 0x0101010101010101ULL) >> 56);
    #pragma unroll
    for (int o = 16; o; o >>= 1) s += __shfl_down_sync(0xFFFFFFFFu, s, o);
    __shared__ unsigned ws[8];
    if ((threadIdx.x & 31) == 0) ws[threadIdx.x >> 5] = s;
    __syncthreads();
    if (threadIdx.x == 0) {
        unsigned t = 0;
        #pragma unroll
        for (int i = 0; i < 8; i++) t += ws[i];
        g_blocksums[blockIdx.x] = t;
    }
}

// Fused scan2+scan3: each block redundantly computes its own global offset
// from the 1024 block sums (cheap), then compacts its 2048 flags.
__global__ void scan23_kernel() {
    unsigned lane = threadIdx.x & 31, wid = threadIdx.x >> 5;

    // block offset = sum of g_blocksums[0 .. blockIdx)
    unsigned partial = 0;
    for (unsigned i = threadIdx.x; i < blockIdx.x; i += 256)
        partial += g_blocksums[i];
    #pragma unroll
    for (int o = 16; o; o >>= 1) partial += __shfl_down_sync(0xFFFFFFFFu, partial, o);
    __shared__ unsigned sred[8];
    __shared__ unsigned s_bof;
    if (lane == 0) sred[wid] = partial;
    __syncthreads();
    if (threadIdx.x == 0) {
        unsigned t = 0;
        #pragma unroll
        for (int i = 0; i < 8; i++) t += sred[i];
        s_bof = t;
    }
    __syncthreads();
    unsigned bof = s_bof;

    // intra-block compaction
    int base = blockIdx.x * 2048 + threadIdx.x * 8;
    unsigned long long v = *(const unsigned long long*)(g_active + base);
    unsigned s = (unsigned)((v * 0x0101010101010101ULL) >> 56);
    unsigned incl = s;
    #pragma unroll
    for (int o = 1; o < 32; o <<= 1) {
        unsigned t = __shfl_up_sync(0xFFFFFFFFu, incl, o);
        if (lane >= (unsigned)o) incl += t;
    }
    unsigned excl = incl - s;
    __shared__ unsigned ws[8];
    if (lane == 31) ws[wid] = incl;
    __syncthreads();
    unsigned woff = 0;
    for (unsigned i = 0; i < wid; i++) woff += ws[i];
    unsigned pos = bof + woff + excl;
    #pragma unroll
    for (int i = 0; i < 8; i++) {
        if ((v >> (i * 8)) & 1ULL) g_cells[pos++] = (unsigned)(base + i);
    }
    // last thread of last block publishes the total count
    if (blockIdx.x == SCAN_BLOCKS - 1 && threadIdx.x == 255)
        g_count = bof + woff + incl;
}

// ---- fused output writer: coords + conv features ------------------------
// Packed dual-fp32 FMA (sm_100+): d = a*b+d on 2 lanes per instruction.
__device__ __forceinline__ void fma_x2(unsigned long long& d,
                                       unsigned long long a,
                                       unsigned long long b) {
    asm("fma.rn.f32x2 %0, %1, %2, %0;" : "+l"(d) : "l"(a), "l"(b));
}

// One thread per output row: 64 channels, depth-3 pipelined tap loop.
__global__ void __launch_bounds__(256, 3)
feat_kernel(const float* __restrict__ kw,
            float* __restrict__ outc,   // [rows,3] coords (may be null)
            float* __restrict__ outf,   // [rows,64] features (may be null)
            int row_base, int row_end) {
    __shared__ float Ks[27 * 64];
    for (int i = threadIdx.x; i < 27 * 64; i += blockDim.x) Ks[i] = kw[i];
    __syncthreads();

    int r = row_base + blockIdx.x * blockDim.x + threadIdx.x;
    if (r >= row_end) return;
    unsigned M = g_count;

    if (r >= (int)M) {
        if (outc) {
            outc[3*r + 0] = 128.0f;
            outc[3*r + 1] = 128.0f;
            outc[3*r + 2] = 128.0f;
        }
        if (outf) {
            float4* o = (float4*)(outf + (size_t)r * 64);
            float4 z4 = make_float4(0.f, 0.f, 0.f, 0.f);
            #pragma unroll
            for (int i = 0; i < 16; i++) o[i] = z4;
        }
        return;
    }

    unsigned lin = g_cells[r];
    int x = lin >> 14, y = (lin >> 7) & 127, z = lin & 127;
    if (outc) {
        outc[3*r + 0] = (float)x;
        outc[3*r + 1] = (float)y;
        outc[3*r + 2] = (float)z;
    }
    if (!outf) return;

    int base = ((x + 1) * PADW + (y + 1)) * PADW + (z + 1);

    unsigned long long acc[32];  // 64 channels as 32 packed fp32 pairs
    #pragma unroll
    for (int j = 0; j < 32; j++) acc[j] = 0ULL;

    // Depth-3 rotating prefetch hides L2 latency behind the FMA/LDS stream.
    float d0 = g_pdensity[base + c_off[0]];
    float d1 = g_pdensity[base + c_off[1]];
    float d2 = g_pdensity[base + c_off[2]];
    #pragma unroll 1
    for (int t = 0; t < 27; t++) {
        float dn = g_pdensity[base + c_off[t + 3]];  // trailing zeros: harmless
        unsigned du = __float_as_uint(d0);
        unsigned long long dd = ((unsigned long long)du << 32) | du;  // (d,d)
        const ulonglong2* K2 = (const ulonglong2*)(Ks + t * 64);
        #pragma unroll
        for (int i = 0; i < 16; i++) {
            ulonglong2 kv = K2[i];               // broadcast LDS.128
            fma_x2(acc[2*i + 0], kv.x, dd);
            fma_x2(acc[2*i + 1], kv.y, dd);
        }
        d0 = d1; d1 = d2; d2 = dn;
    }

    ulonglong2* o = (ulonglong2*)(outf + (size_t)r * 64);
    #pragma unroll
    for (int i = 0; i < 16; i++) {
        ulonglong2 v; v.x = acc[2*i]; v.y = acc[2*i + 1];
        o[i] = v;
    }
}

// ---------------------------------------------------------------------------
extern "C" void kernel_launch(void* const* d_in, const int* in_sizes, int n_in,
                              void* d_out, int out_size) {
    const int*   indices  = (const int*)d_in[0];    // [N,3] int32
    const float* features = (const float*)d_in[1];  // [N,1] float32
    const float* kw       = (const float*)d_in[2];  // [3,3,3,1,64] float32

    int n = in_sizes[0] / 3;
    int rows = n * 27;
    float* out = (float*)d_out;

    // zero density + active via memset nodes
    void* p_density = nullptr;
    void* p_active  = nullptr;
    cudaGetSymbolAddress(&p_density, g_pdensity);
    cudaGetSymbolAddress(&p_active,  g_active);
    cudaMemsetAsync(p_density, 0, PGRID_N * sizeof(float));
    cudaMemsetAsync(p_active,  0, GRID_N);

    scatter_kernel<<<(n + 255) / 256, 256>>>(indices, features, n);
    scan1_kernel<<<SCAN_BLOCKS, 256>>>();
    scan23_kernel<<<SCAN_BLOCKS, 256>>>();

    // feat split into two half-range launches (slots #6 and #7 for ncu).
    int half = (rows / 2 + 255) & ~255;   // multiple of block size
    if (half > rows) half = rows;
    float* outc0 = nullptr; float* outf0 = nullptr;
    if (out_size == rows * 64) {
        outf0 = out;
    } else if (out_size == rows * 3) {
        outc0 = out;
    } else {
        outc0 = out; outf0 = out + (size_t)rows * 3;
    }
    int b1 = (half + 255) / 256;
    int b2 = (rows - half + 255) / 256;
    if (b1 > 0) feat_kernel<<<b1, 256>>>(kw, outc0, outf0, 0, half);
    if (b2 > 0) feat_kernel<<<b2, 256>>>(kw, outc0, outf0, half, rows);
}

// round 9
// speedup vs baseline: 1.0651x; 1.0651x over previous
#include <cuda_runtime.h>
#include <cstdint>

// Grid is 128^3 logical; density padded to 130^3 (zero border) plus a
// trailing guaranteed-zero guard window for inactive rows in mixed quads.
#define GRID_N (128*128*128)          // 2,097,152
#define PADW   130
#define PGRID_N (PADW*PADW*PADW)      // 2,197,000
#define GUARD_EXTRA 34200
#define SAFE_BASE (PGRID_N + 17060)   // SAFE_BASE + c_off[t] stays inside guard
#define DENS_TOTAL (PGRID_N + GUARD_EXTRA)
#define SCAN_BLOCKS 1024              // 1024 * 256 * 8 = 2,097,152

__device__ float g_pdensity[DENS_TOTAL];
__device__ __align__(8) unsigned char g_active[GRID_N];
__device__ unsigned int g_blocksums[SCAN_BLOCKS];
__device__ unsigned int g_count;
__device__ unsigned int g_cells[GRID_N];

// neighbor offsets in padded grid: di*16900 + dj*130 + dk, t=(di+1)*9+(dj+1)*3+(dk+1)
// (trailing zeros so the depth-2 prefetch can read t+2 unconditionally)
__constant__ int c_off[30] = {
    -17031,-17030,-17029,-16901,-16900,-16899,-16771,-16770,-16769,
      -131,  -130,  -129,    -1,     0,     1,   129,   130,   131,
     16769, 16770, 16771, 16899, 16900, 16901, 17029, 17030, 17031,
     0, 0, 0};

// ---------------------------------------------------------------------------
__global__ void scatter_kernel(const int* __restrict__ idx,
                               const float* __restrict__ feat, int n) {
    int i = blockIdx.x * blockDim.x + threadIdx.x;
    if (i >= n) return;
    int x = idx[3*i], y = idx[3*i+1], z = idx[3*i+2];
    int plin = ((x + 1) * PADW + (y + 1)) * PADW + (z + 1);
    atomicAdd(&g_pdensity[plin], feat[i]);
    #pragma unroll
    for (int di = -1; di <= 1; di++)
        #pragma unroll
        for (int dj = -1; dj <= 1; dj++)
            #pragma unroll
            for (int dk = -1; dk <= 1; dk++) {
                int nx = x + di, ny = y + dj, nz = z + dk;
                if ((unsigned)nx < 128u && (unsigned)ny < 128u && (unsigned)nz < 128u)
                    g_active[(nx << 14) | (ny << 7) | nz] = 1;  // racy stores of 1: fine
            }
}

// ---- prefix scan over 2M flags: 2 kernels -------------------------------
__global__ void scan1_kernel() {
    int base = blockIdx.x * 2048 + threadIdx.x * 8;
    unsigned long long v = *(const unsigned long long*)(g_active + base);
    unsigned s = (unsigned)((v * 0x0101010101010101ULL) >> 56);
    #pragma unroll
    for (int o = 16; o; o >>= 1) s += __shfl_down_sync(0xFFFFFFFFu, s, o);
    __shared__ unsigned ws[8];
    if ((threadIdx.x & 31) == 0) ws[threadIdx.x >> 5] = s;
    __syncthreads();
    if (threadIdx.x == 0) {
        unsigned t = 0;
        #pragma unroll
        for (int i = 0; i < 8; i++) t += ws[i];
        g_blocksums[blockIdx.x] = t;
    }
}

// Fused scan2+scan3: each block redundantly computes its own global offset
// from the 1024 block sums, then compacts its 2048 flags.
__global__ void scan23_kernel() {
    unsigned lane = threadIdx.x & 31, wid = threadIdx.x >> 5;

    unsigned partial = 0;
    for (unsigned i = threadIdx.x; i < blockIdx.x; i += 256)
        partial += g_blocksums[i];
    #pragma unroll
    for (int o = 16; o; o >>= 1) partial += __shfl_down_sync(0xFFFFFFFFu, partial, o);
    __shared__ unsigned sred[8];
    __shared__ unsigned s_bof;
    if (lane == 0) sred[wid] = partial;
    __syncthreads();
    if (threadIdx.x == 0) {
        unsigned t = 0;
        #pragma unroll
        for (int i = 0; i < 8; i++) t += sred[i];
        s_bof = t;
    }
    __syncthreads();
    unsigned bof = s_bof;

    int base = blockIdx.x * 2048 + threadIdx.x * 8;
    unsigned long long v = *(const unsigned long long*)(g_active + base);
    unsigned s = (unsigned)((v * 0x0101010101010101ULL) >> 56);
    unsigned incl = s;
    #pragma unroll
    for (int o = 1; o < 32; o <<= 1) {
        unsigned t = __shfl_up_sync(0xFFFFFFFFu, incl, o);
        if (lane >= (unsigned)o) incl += t;
    }
    unsigned excl = incl - s;
    __shared__ unsigned ws[8];
    if (lane == 31) ws[wid] = incl;
    __syncthreads();
    unsigned woff = 0;
    for (unsigned i = 0; i < wid; i++) woff += ws[i];
    unsigned pos = bof + woff + excl;
    #pragma unroll
    for (int i = 0; i < 8; i++) {
        if ((v >> (i * 8)) & 1ULL) g_cells[pos++] = (unsigned)(base + i);
    }
    if (blockIdx.x == SCAN_BLOCKS - 1 && threadIdx.x == 255)
        g_count = bof + woff + incl;
}

// ---- fused output writer ------------------------------------------------
// Packed dual-fp32 FMA (sm_100+).
__device__ __forceinline__ void fma_x2(unsigned long long& d,
                                       unsigned long long a,
                                       unsigned long long b) {
    asm("fma.rn.f32x2 %0, %1, %2, %0;" : "+l"(d) : "l"(a), "l"(b));
}
__device__ __forceinline__ unsigned long long pack2(float f) {
    unsigned u = __float_as_uint(f);
    return ((unsigned long long)u << 32) | u;
}

// Thread = (row-quad, channel-sixteenth): 4 rows x 16 channels.
// Each LDS.128 weight load feeds 4 rows -> 108 LDS.128/thread (was 432).
__global__ void __launch_bounds__(256, 2)
feat_kernel(const float* __restrict__ kw,
            float* __restrict__ outc,   // [rows,3] coords (may be null)
            float* __restrict__ outf,   // [rows,64] features (may be null)
            int row_base, int row_end) {
    __shared__ float Ks[27 * 64];
    for (int i = threadIdx.x; i < 27 * 64; i += blockDim.x) Ks[i] = kw[i];
    __syncthreads();

    int gid = row_base + blockIdx.x * blockDim.x + threadIdx.x;
    if (gid >= row_end) return;
    int rs = gid & ~3;         // first row of this thread's quad
    int cg = gid & 3;          // channel group (16 channels)
    unsigned M = g_count;

    int bases[4];
    bool any = false;
    #pragma unroll
    for (int j = 0; j < 4; j++) {
        int r = rs + j;
        bool act = r < (int)M;
        unsigned lin = act ? g_cells[r] : 0u;
        int x = lin >> 14, y = (lin >> 7) & 127, z = lin & 127;
        if (outc && cg == 0) {
            outc[3*r + 0] = act ? (float)x : 128.0f;
            outc[3*r + 1] = act ? (float)y : 128.0f;
            outc[3*r + 2] = act ? (float)z : 128.0f;
        }
        bases[j] = act ? (((x + 1) * PADW + (y + 1)) * PADW + (z + 1)) : SAFE_BASE;
        any |= act;
    }
    if (!outf) return;

    if (!any) {  // whole quad inactive: zero-fill fast path
        float4 z4 = make_float4(0.f, 0.f, 0.f, 0.f);
        #pragma unroll
        for (int j = 0; j < 4; j++) {
            float4* o = (float4*)(outf + (size_t)(rs + j) * 64 + cg * 16);
            o[0] = z4; o[1] = z4; o[2] = z4; o[3] = z4;
        }
        return;
    }

    unsigned long long acc[32];  // 4 rows x 16 ch = 4 x 8 packed pairs
    #pragma unroll
    for (int j = 0; j < 32; j++) acc[j] = 0ULL;

    const float* Kp = Ks + cg * 16;

    // Depth-2 rotating prefetch per row.
    float d0[4], d1[4];
    #pragma unroll
    for (int j = 0; j < 4; j++) {
        d0[j] = g_pdensity[bases[j] + c_off[0]];
        d1[j] = g_pdensity[bases[j] + c_off[1]];
    }
    #pragma unroll 1
    for (int t = 0; t < 27; t++) {
        float dn[4];
        #pragma unroll
        for (int j = 0; j < 4; j++) dn[j] = g_pdensity[bases[j] + c_off[t + 2]];
        const ulonglong2* K2 = (const ulonglong2*)(Kp + t * 64);
        ulonglong2 k0 = K2[0], k1 = K2[1], k2 = K2[2], k3 = K2[3];  // 16 weights
        #pragma unroll
        for (int j = 0; j < 4; j++) {
            unsigned long long dd = pack2(d0[j]);
            fma_x2(acc[j*8 + 0], k0.x, dd);
            fma_x2(acc[j*8 + 1], k0.y, dd);
            fma_x2(acc[j*8 + 2], k1.x, dd);
            fma_x2(acc[j*8 + 3], k1.y, dd);
            fma_x2(acc[j*8 + 4], k2.x, dd);
            fma_x2(acc[j*8 + 5], k2.y, dd);
            fma_x2(acc[j*8 + 6], k3.x, dd);
            fma_x2(acc[j*8 + 7], k3.y, dd);
            d0[j] = d1[j]; d1[j] = dn[j];
        }
    }

    #pragma unroll
    for (int j = 0; j < 4; j++) {
        ulonglong2* o = (ulonglong2*)(outf + (size_t)(rs + j) * 64 + cg * 16);
        ulonglong2 v;
        v.x = acc[j*8 + 0]; v.y = acc[j*8 + 1]; o[0] = v;
        v.x = acc[j*8 + 2]; v.y = acc[j*8 + 3]; o[1] = v;
        v.x = acc[j*8 + 4]; v.y = acc[j*8 + 5]; o[2] = v;
        v.x = acc[j*8 + 6]; v.y = acc[j*8 + 7]; o[3] = v;
    }
}

// ---------------------------------------------------------------------------
extern "C" void kernel_launch(void* const* d_in, const int* in_sizes, int n_in,
                              void* d_out, int out_size) {
    const int*   indices  = (const int*)d_in[0];    // [N,3] int32
    const float* features = (const float*)d_in[1];  // [N,1] float32
    const float* kw       = (const float*)d_in[2];  // [3,3,3,1,64] float32

    int n = in_sizes[0] / 3;
    int rows = n * 27;
    float* out = (float*)d_out;

    // zero density (incl. guard window) + active via memset nodes
    void* p_density = nullptr;
    void* p_active  = nullptr;
    cudaGetSymbolAddress(&p_density, g_pdensity);
    cudaGetSymbolAddress(&p_active,  g_active);
    cudaMemsetAsync(p_density, 0, DENS_TOTAL * sizeof(float));
    cudaMemsetAsync(p_active,  0, GRID_N);

    scatter_kernel<<<(n + 255) / 256, 256>>>(indices, features, n);
    scan1_kernel<<<SCAN_BLOCKS, 256>>>();
    scan23_kernel<<<SCAN_BLOCKS, 256>>>();

    // feat split into two half-range launches (keeps feat in ncu's slot).
    int half = (rows / 2 + 255) & ~255;   // multiple of 256 (and of 4)
    if (half > rows) half = rows;
    float* outc0 = nullptr; float* outf0 = nullptr;
    if (out_size == rows * 64) {
        outf0 = out;
    } else if (out_size == rows * 3) {
        outc0 = out;
    } else {
        outc0 = out; outf0 = out + (size_t)rows * 3;
    }
    int b1 = (half + 255) / 256;
    int b2 = (rows - half + 255) / 256;
    if (b1 > 0) feat_kernel<<<b1, 256>>>(kw, outc0, outf0, 0, half);
    if (b2 > 0) feat_kernel<<<b2, 256>>>(kw, outc0, outf0, half, rows);
}